// round 4
// baseline (speedup 1.0000x reference)
#include <cuda_runtime.h>

#define N_NODES 2048
#define F_IN    64
#define H_DIM   16
#define O_DIM   8

// -------- scratch (no allocations allowed) --------
__device__ float g_fsums[N_NODES * O_DIM];   // [N, O] f-branch sums

// ============================================================================
// Kernel 1: f-branch. grid=128, block=256. Block handles 16 nodes;
// thread (node = tid>>4, feats = (tid&15)*4 .. +4). All SMs active.
//
// Fast path (all f-biases zero — true here): per-feature 1->16->16->8 relu
// MLP with zero biases collapses EXACTLY to
//   fx[o] = max(x,0)*A+[f,o] + min(x,0)*A-[f,o]
// Fold A+/A- computed per block from L2-hot weights (~96KB reads/block).
// Slow path: honest full MLP chain.
// ============================================================================
__global__ void __launch_bounds__(256)
k_fsum(const float* __restrict__ x,
       const float* __restrict__ fW1, const float* __restrict__ fb1,
       const float* __restrict__ fW2, const float* __restrict__ fb2,
       const float* __restrict__ fW3, const float* __restrict__ fb3)
{
    __shared__ float sA[F_IN][16];       // [f][0..7]=A+, [f][8..15]=A-

    const int tid = threadIdx.x;

    // ---- runtime guard: all f-biases zero? ----
    int nz = 0;
    for (int i = tid; i < F_IN * H_DIM; i += 256)
        nz |= (fb1[i] != 0.0f) | (fb2[i] != 0.0f);
    for (int i = tid; i < F_IN * O_DIM; i += 256)
        nz |= (fb3[i] != 0.0f);
    const int any_nz = __syncthreads_or(nz);

    const int node = blockIdx.x * 16 + (tid >> 4);
    const int fbase = (tid & 15) * 4;

    float acc[O_DIM];
    #pragma unroll
    for (int o = 0; o < O_DIM; o++) acc[o] = 0.0f;

    if (!any_nz) {
        // ---- fold: thread t handles f = t>>2, g-range (t&3)*4..+4 ----
        {
            const int f    = tid >> 2;
            const int part = tid & 3;
            float cp[4], cn[4];
            #pragma unroll
            for (int gi = 0; gi < 4; gi++) {
                const int g = part * 4 + gi;
                float sp = 0.0f, sn = 0.0f;
                #pragma unroll
                for (int h = 0; h < H_DIM; h++) {
                    const float w2 = __ldg(fW2 + (f * H_DIM + g) * H_DIM + h);
                    const float w1 = __ldg(fW1 + f * H_DIM + h);
                    sp = fmaf(w2, fmaxf(w1, 0.0f), sp);
                    sn = fmaf(w2, fminf(w1, 0.0f), sn);
                }
                cp[gi] = fmaxf(sp, 0.0f);
                cn[gi] = fminf(sn, 0.0f);
            }
            #pragma unroll
            for (int o = 0; o < O_DIM; o++) {
                float sa = 0.0f, sb = 0.0f;
                #pragma unroll
                for (int gi = 0; gi < 4; gi++) {
                    const float w3 = __ldg(fW3 + (f * O_DIM + o) * H_DIM + part * 4 + gi);
                    sa = fmaf(w3, cp[gi], sa);
                    sb = fmaf(w3, cn[gi], sb);
                }
                // reduce 4 parts (lanes part 0..3 within warp)
                sa += __shfl_xor_sync(0xFFFFFFFFu, sa, 1);
                sa += __shfl_xor_sync(0xFFFFFFFFu, sa, 2);
                sb += __shfl_xor_sync(0xFFFFFFFFu, sb, 1);
                sb += __shfl_xor_sync(0xFFFFFFFFu, sb, 2);
                if (part == 0) { sA[f][o] = sa; sA[f][8 + o] = sb; }
            }
        }
        __syncthreads();

        // ---- relu-split GEMV: this thread's 4 features of its node ----
        // x offset = node*64 + fbase = tid*4 relative to block base: coalesced
        const float4 xv4 = __ldg((const float4*)(x + (size_t)node * F_IN + fbase));
        const float xv[4] = { xv4.x, xv4.y, xv4.z, xv4.w };
        #pragma unroll
        for (int ff = 0; ff < 4; ff++) {
            const int   f  = fbase + ff;
            const float xp = fmaxf(xv[ff], 0.0f);
            const float xn = fminf(xv[ff], 0.0f);
            #pragma unroll
            for (int o = 0; o < O_DIM; o++)
                acc[o] = fmaf(xp, sA[f][o], fmaf(xn, sA[f][8 + o], acc[o]));
        }
    } else {
        // ---- honest fallback: full per-feature MLP chain ----
        for (int ff = 0; ff < 4; ff++) {
            const int   f  = fbase + ff;
            const float xv = x[(size_t)node * F_IN + f];
            float h1[H_DIM];
            #pragma unroll
            for (int k = 0; k < H_DIM; k++)
                h1[k] = fmaxf(fmaf(xv, __ldg(fW1 + f*H_DIM + k), __ldg(fb1 + f*H_DIM + k)), 0.0f);
            float h2[H_DIM];
            #pragma unroll
            for (int g = 0; g < H_DIM; g++) {
                float s = __ldg(fb2 + f*H_DIM + g);
                #pragma unroll
                for (int k = 0; k < H_DIM; k++)
                    s = fmaf(__ldg(fW2 + (f*H_DIM + g)*H_DIM + k), h1[k], s);
                h2[g] = fmaxf(s, 0.0f);
            }
            #pragma unroll
            for (int o = 0; o < O_DIM; o++) {
                float s = __ldg(fb3 + f*O_DIM + o);
                #pragma unroll
                for (int k = 0; k < H_DIM; k++)
                    s = fmaf(__ldg(fW3 + (f*O_DIM + o)*H_DIM + k), h2[k], s);
                acc[o] += s;
            }
        }
    }

    // ---- reduce 16 feature-threads per node (within-warp butterfly) ----
    #pragma unroll
    for (int o = 0; o < O_DIM; o++) {
        acc[o] += __shfl_xor_sync(0xFFFFFFFFu, acc[o], 8);
        acc[o] += __shfl_xor_sync(0xFFFFFFFFu, acc[o], 4);
        acc[o] += __shfl_xor_sync(0xFFFFFFFFu, acc[o], 2);
        acc[o] += __shfl_xor_sync(0xFFFFFFFFu, acc[o], 1);
    }
    if ((tid & 15) < 8) {
        const int o = tid & 7;
        float v = 0.0f;
        #pragma unroll
        for (int q = 0; q < O_DIM; q++)
            if (q == o) v = acc[q];
        g_fsums[node * O_DIM + o] = v;
    }
}

// ============================================================================
// Helper: full scalar m-MLP (fallback path only; never taken here)
// ============================================================================
__device__ __forceinline__ float m_eval_full(float d,
    const float* sw1, const float* sb1, const float* sw2,
    const float* sb2, const float* sw3, float b3)
{
    float h1[H_DIM];
    #pragma unroll
    for (int k = 0; k < H_DIM; k++)
        h1[k] = fmaxf(fmaf(d, sw1[k], sb1[k]), 0.0f);
    float m = b3;
    #pragma unroll
    for (int g = 0; g < H_DIM; g++) {
        float s = sb2[g];
        #pragma unroll
        for (int k = 0; k < H_DIM; k++)
            s = fmaf(sw2[g * H_DIM + k], h1[k], s);
        m = fmaf(sw3[g], fmaxf(s, 0.0f), m);
    }
    return m;
}

// ============================================================================
// Kernel 2: pred[i,:] = sum_j ( m(d[i,j]) / norm[i,j] ) * f_sums[j,:]
// grid=512 blocks, 4 rows/block. launch_bounds(256,2) caps regs at 128 ->
// 2 CTAs/SM, 16 warps, enough MLP to reach the HBM/LTS floor (~6us for
// 33.5MB DRAM + 32MB L2-resident f_sums re-reads).
// Loads front-batched; d/norm use __ldcs (streaming).
// ============================================================================
__global__ void __launch_bounds__(256, 2)
k_main(const float* __restrict__ dmat, const float* __restrict__ nmat,
       const float* __restrict__ mW1, const float* __restrict__ mb1,
       const float* __restrict__ mW2, const float* __restrict__ mb2,
       const float* __restrict__ mW3, const float* __restrict__ mb3,
       float* __restrict__ out)
{
    __shared__ float s_ap, s_an, s_beta;
    __shared__ int   s_fast;
    __shared__ float sred[8][32];
    __shared__ float sw1[H_DIM], sb1v[H_DIM], sw2[H_DIM * H_DIM], sb2v[H_DIM], sw3[H_DIM];

    const int tid = threadIdx.x;

    // ---- warp 0: fold m-MLP + zero-bias check (weights L2-hot) ----
    if (tid < 32) {
        const int g = tid & 15;
        float cp = 0.0f, cn = 0.0f;
        #pragma unroll
        for (int h = 0; h < H_DIM; h++) {
            const float w2 = __ldg(mW2 + g * H_DIM + h);
            const float w1 = __ldg(mW1 + h);
            cp = fmaf(w2, fmaxf(w1, 0.0f), cp);
            cn = fmaf(w2, fminf(w1, 0.0f), cn);
        }
        const float w3 = __ldg(mW3 + g);
        float ap = w3 * fmaxf(cp, 0.0f);
        float an = w3 * fminf(cn, 0.0f);
        #pragma unroll
        for (int off = 8; off > 0; off >>= 1) {
            ap += __shfl_xor_sync(0xFFFFFFFFu, ap, off);
            an += __shfl_xor_sync(0xFFFFFFFFu, an, off);
        }
        int z = (__ldg(mb1 + g) == 0.0f) & (__ldg(mb2 + g) == 0.0f);
        z = __all_sync(0xFFFFFFFFu, z);
        if (tid == 0) { s_ap = ap; s_an = an; s_beta = __ldg(mb3); s_fast = z; }
    }
    __syncthreads();

    const int i0 = blockIdx.x * 4;

    float acc[4][O_DIM];
    #pragma unroll
    for (int r = 0; r < 4; r++)
        #pragma unroll
        for (int o = 0; o < O_DIM; o++) acc[r][o] = 0.0f;

    if (s_fast) {
        const float ap = s_ap, an = s_an, be = s_beta;
        #pragma unroll
        for (int jt = 0; jt < 2; jt++) {
            const int j0 = jt * 1024 + tid * 4;

            // front-batched loads: 8 fs + 4 d + 4 n float4
            float4 fs[8];
            const float4* fp = (const float4*)(g_fsums + j0 * O_DIM);
            #pragma unroll
            for (int q = 0; q < 8; q++) fs[q] = fp[q];

            float4 dv[4], nv[4];
            #pragma unroll
            for (int r = 0; r < 4; r++) {
                dv[r] = __ldcs((const float4*)(dmat + (size_t)(i0 + r) * N_NODES + j0));
                nv[r] = __ldcs((const float4*)(nmat + (size_t)(i0 + r) * N_NODES + j0));
            }

            #pragma unroll
            for (int r = 0; r < 4; r++) {
                const float w0 = __fdividef(fmaf(ap, fmaxf(dv[r].x, 0.f), fmaf(an, fminf(dv[r].x, 0.f), be)), nv[r].x);
                const float w1 = __fdividef(fmaf(ap, fmaxf(dv[r].y, 0.f), fmaf(an, fminf(dv[r].y, 0.f), be)), nv[r].y);
                const float w2 = __fdividef(fmaf(ap, fmaxf(dv[r].z, 0.f), fmaf(an, fminf(dv[r].z, 0.f), be)), nv[r].z);
                const float w3 = __fdividef(fmaf(ap, fmaxf(dv[r].w, 0.f), fmaf(an, fminf(dv[r].w, 0.f), be)), nv[r].w);
                #pragma unroll
                for (int o = 0; o < 4; o++) {
                    acc[r][o]   = fmaf(w0, (&fs[0].x)[o], acc[r][o]);
                    acc[r][4+o] = fmaf(w0, (&fs[1].x)[o], acc[r][4+o]);
                    acc[r][o]   = fmaf(w1, (&fs[2].x)[o], acc[r][o]);
                    acc[r][4+o] = fmaf(w1, (&fs[3].x)[o], acc[r][4+o]);
                    acc[r][o]   = fmaf(w2, (&fs[4].x)[o], acc[r][o]);
                    acc[r][4+o] = fmaf(w2, (&fs[5].x)[o], acc[r][4+o]);
                    acc[r][o]   = fmaf(w3, (&fs[6].x)[o], acc[r][o]);
                    acc[r][4+o] = fmaf(w3, (&fs[7].x)[o], acc[r][4+o]);
                }
            }
        }
    } else {
        // ---- honest fallback: full per-pair m-MLP (may spill; never taken) ----
        if (tid < H_DIM) {
            sw1[tid]  = mW1[tid]; sb1v[tid] = mb1[tid];
            sb2v[tid] = mb2[tid]; sw3[tid]  = mW3[tid];
        }
        sw2[tid] = mW2[tid];
        __syncthreads();
        const float b3v = mb3[0];

        for (int jt = 0; jt < 2; jt++) {
            const int j0 = jt * 1024 + tid * 4;
            float4 fs[8];
            const float4* fp = (const float4*)(g_fsums + j0 * O_DIM);
            #pragma unroll
            for (int q = 0; q < 8; q++) fs[q] = fp[q];

            for (int r = 0; r < 4; r++) {
                const float4 d4 = *(const float4*)(dmat + (size_t)(i0 + r) * N_NODES + j0);
                const float4 n4 = *(const float4*)(nmat + (size_t)(i0 + r) * N_NODES + j0);
                float w[4];
                w[0] = __fdividef(m_eval_full(d4.x, sw1, sb1v, sw2, sb2v, sw3, b3v), n4.x);
                w[1] = __fdividef(m_eval_full(d4.y, sw1, sb1v, sw2, sb2v, sw3, b3v), n4.y);
                w[2] = __fdividef(m_eval_full(d4.z, sw1, sb1v, sw2, sb2v, sw3, b3v), n4.z);
                w[3] = __fdividef(m_eval_full(d4.w, sw1, sb1v, sw2, sb2v, sw3, b3v), n4.w);
                #pragma unroll
                for (int q = 0; q < 4; q++)
                    #pragma unroll
                    for (int o = 0; o < 4; o++) {
                        acc[r][o]   = fmaf(w[q], (&fs[q*2].x)[o],   acc[r][o]);
                        acc[r][4+o] = fmaf(w[q], (&fs[q*2+1].x)[o], acc[r][4+o]);
                    }
            }
        }
    }

    // ---- block reduction: warp butterfly, then 8 warps via smem ----
    #pragma unroll
    for (int r = 0; r < 4; r++)
        #pragma unroll
        for (int o = 0; o < O_DIM; o++)
            #pragma unroll
            for (int off = 16; off > 0; off >>= 1)
                acc[r][o] += __shfl_xor_sync(0xFFFFFFFFu, acc[r][o], off);

    const int warp = tid >> 5;
    const int lane = tid & 31;
    if (lane == 0) {
        #pragma unroll
        for (int r = 0; r < 4; r++)
            #pragma unroll
            for (int o = 0; o < O_DIM; o++)
                sred[warp][r * O_DIM + o] = acc[r][o];
    }
    __syncthreads();
    if (tid < 32) {
        float s = 0.0f;
        #pragma unroll
        for (int w = 0; w < 8; w++) s += sred[w][tid];
        const int r = tid >> 3;
        const int o = tid & 7;
        out[(i0 + r) * O_DIM + o] = s;
    }
}

// ============================================================================
// launch
// ============================================================================
extern "C" void kernel_launch(void* const* d_in, const int* in_sizes, int n_in,
                              void* d_out, int out_size)
{
    const float* x   = (const float*)d_in[0];
    const float* dm  = (const float*)d_in[1];
    const float* nm  = (const float*)d_in[2];
    const float* fW1 = (const float*)d_in[3];
    const float* fb1 = (const float*)d_in[4];
    const float* fW2 = (const float*)d_in[5];
    const float* fb2 = (const float*)d_in[6];
    const float* fW3 = (const float*)d_in[7];
    const float* fb3 = (const float*)d_in[8];
    const float* mW1 = (const float*)d_in[9];
    const float* mb1 = (const float*)d_in[10];
    const float* mW2 = (const float*)d_in[11];
    const float* mb2 = (const float*)d_in[12];
    const float* mW3 = (const float*)d_in[13];
    const float* mb3 = (const float*)d_in[14];
    float* out = (float*)d_out;

    k_fsum<<<128, 256>>>(x, fW1, fb1, fW2, fb2, fW3, fb3);
    k_main<<<512, 256>>>(dm, nm, mW1, mb1, mW2, mb2, mW3, mb3, out);
}

// round 5
// speedup vs baseline: 1.1342x; 1.1342x over previous
#include <cuda_runtime.h>

#define N_NODES 2048
#define F_IN    64
#define H_DIM   16
#define O_DIM   8

// -------- scratch (no allocations allowed) --------
__device__ float g_fsums[N_NODES * O_DIM];   // [N, O] f-branch sums

// ============================================================================
// Kernel 1: f-branch. grid=128, block=256. Block handles 16 nodes.
// Fast path (all f-biases zero — true here): per-feature 1->16->16->8 relu
// MLP with zero biases collapses EXACTLY to
//   fx[o] = max(x,0)*A+[f,o] + min(x,0)*A-[f,o]
// ============================================================================
__global__ void __launch_bounds__(256)
k_fsum(const float* __restrict__ x,
       const float* __restrict__ fW1, const float* __restrict__ fb1,
       const float* __restrict__ fW2, const float* __restrict__ fb2,
       const float* __restrict__ fW3, const float* __restrict__ fb3)
{
    __shared__ float sA[F_IN][16];       // [f][0..7]=A+, [f][8..15]=A-

    const int tid = threadIdx.x;

    // ---- runtime guard: all f-biases zero? ----
    int nz = 0;
    for (int i = tid; i < F_IN * H_DIM; i += 256)
        nz |= (fb1[i] != 0.0f) | (fb2[i] != 0.0f);
    for (int i = tid; i < F_IN * O_DIM; i += 256)
        nz |= (fb3[i] != 0.0f);
    const int any_nz = __syncthreads_or(nz);

    const int node = blockIdx.x * 16 + (tid >> 4);
    const int fbase = (tid & 15) * 4;

    float acc[O_DIM];
    #pragma unroll
    for (int o = 0; o < O_DIM; o++) acc[o] = 0.0f;

    if (!any_nz) {
        // ---- fold: thread t handles f = t>>2, g-range (t&3)*4..+4 ----
        {
            const int f    = tid >> 2;
            const int part = tid & 3;
            float cp[4], cn[4];
            #pragma unroll
            for (int gi = 0; gi < 4; gi++) {
                const int g = part * 4 + gi;
                float sp = 0.0f, sn = 0.0f;
                #pragma unroll
                for (int h = 0; h < H_DIM; h++) {
                    const float w2 = __ldg(fW2 + (f * H_DIM + g) * H_DIM + h);
                    const float w1 = __ldg(fW1 + f * H_DIM + h);
                    sp = fmaf(w2, fmaxf(w1, 0.0f), sp);
                    sn = fmaf(w2, fminf(w1, 0.0f), sn);
                }
                cp[gi] = fmaxf(sp, 0.0f);
                cn[gi] = fminf(sn, 0.0f);
            }
            #pragma unroll
            for (int o = 0; o < O_DIM; o++) {
                float sa = 0.0f, sb = 0.0f;
                #pragma unroll
                for (int gi = 0; gi < 4; gi++) {
                    const float w3 = __ldg(fW3 + (f * O_DIM + o) * H_DIM + part * 4 + gi);
                    sa = fmaf(w3, cp[gi], sa);
                    sb = fmaf(w3, cn[gi], sb);
                }
                sa += __shfl_xor_sync(0xFFFFFFFFu, sa, 1);
                sa += __shfl_xor_sync(0xFFFFFFFFu, sa, 2);
                sb += __shfl_xor_sync(0xFFFFFFFFu, sb, 1);
                sb += __shfl_xor_sync(0xFFFFFFFFu, sb, 2);
                if (part == 0) { sA[f][o] = sa; sA[f][8 + o] = sb; }
            }
        }
        __syncthreads();

        // ---- relu-split GEMV: this thread's 4 features of its node ----
        const float4 xv4 = __ldg((const float4*)(x + (size_t)node * F_IN + fbase));
        const float xv[4] = { xv4.x, xv4.y, xv4.z, xv4.w };
        #pragma unroll
        for (int ff = 0; ff < 4; ff++) {
            const int   f  = fbase + ff;
            const float xp = fmaxf(xv[ff], 0.0f);
            const float xn = fminf(xv[ff], 0.0f);
            #pragma unroll
            for (int o = 0; o < O_DIM; o++)
                acc[o] = fmaf(xp, sA[f][o], fmaf(xn, sA[f][8 + o], acc[o]));
        }
    } else {
        // ---- honest fallback: full per-feature MLP chain ----
        for (int ff = 0; ff < 4; ff++) {
            const int   f  = fbase + ff;
            const float xv = x[(size_t)node * F_IN + f];
            float h1[H_DIM];
            #pragma unroll
            for (int k = 0; k < H_DIM; k++)
                h1[k] = fmaxf(fmaf(xv, __ldg(fW1 + f*H_DIM + k), __ldg(fb1 + f*H_DIM + k)), 0.0f);
            float h2[H_DIM];
            #pragma unroll
            for (int g = 0; g < H_DIM; g++) {
                float s = __ldg(fb2 + f*H_DIM + g);
                #pragma unroll
                for (int k = 0; k < H_DIM; k++)
                    s = fmaf(__ldg(fW2 + (f*H_DIM + g)*H_DIM + k), h1[k], s);
                h2[g] = fmaxf(s, 0.0f);
            }
            #pragma unroll
            for (int o = 0; o < O_DIM; o++) {
                float s = __ldg(fb3 + f*O_DIM + o);
                #pragma unroll
                for (int k = 0; k < H_DIM; k++)
                    s = fmaf(__ldg(fW3 + (f*O_DIM + o)*H_DIM + k), h2[k], s);
                acc[o] += s;
            }
        }
    }

    // ---- reduce 16 feature-threads per node ----
    #pragma unroll
    for (int o = 0; o < O_DIM; o++) {
        acc[o] += __shfl_xor_sync(0xFFFFFFFFu, acc[o], 8);
        acc[o] += __shfl_xor_sync(0xFFFFFFFFu, acc[o], 4);
        acc[o] += __shfl_xor_sync(0xFFFFFFFFu, acc[o], 2);
        acc[o] += __shfl_xor_sync(0xFFFFFFFFu, acc[o], 1);
    }
    if ((tid & 15) < 8) {
        const int o = tid & 7;
        float v = 0.0f;
        #pragma unroll
        for (int q = 0; q < O_DIM; q++)
            if (q == o) v = acc[q];
        g_fsums[node * O_DIM + o] = v;
    }
}

// ============================================================================
// Helper: full scalar m-MLP (fallback path only; never taken here)
// ============================================================================
__device__ __forceinline__ float m_eval_full(float d,
    const float* sw1, const float* sb1, const float* sw2,
    const float* sb2, const float* sw3, float b3)
{
    float h1[H_DIM];
    #pragma unroll
    for (int k = 0; k < H_DIM; k++)
        h1[k] = fmaxf(fmaf(d, sw1[k], sb1[k]), 0.0f);
    float m = b3;
    #pragma unroll
    for (int g = 0; g < H_DIM; g++) {
        float s = sb2[g];
        #pragma unroll
        for (int k = 0; k < H_DIM; k++)
            s = fmaf(sw2[g * H_DIM + k], h1[k], s);
        m = fmaf(sw3[g], fmaxf(s, 0.0f), m);
    }
    return m;
}

// ============================================================================
// Kernel 2: pred[i,:] = sum_j ( m(d[i,j]) / norm[i,j] ) * f_sums[j,:]
// grid=512 blocks, 4 rows/block, 2 CTAs/SM.
//
// R4 lesson: per-thread f_sums LDG.128s had lanes strided 128B -> 32 lines
// per instruction (8x L1 wavefront amplification) -> L1tex queue clogged ->
// DRAM stuck at 17% regardless of occupancy. Fix: stage each 32KB half of
// f_sums through SMEM with one coalesced pass (SW128-swizzled), consume via
// conflict-free LDS.128. d/norm stay as coalesced __ldcs float4 streams.
// ============================================================================
__global__ void __launch_bounds__(256, 2)
k_main(const float* __restrict__ dmat, const float* __restrict__ nmat,
       const float* __restrict__ mW1, const float* __restrict__ mb1,
       const float* __restrict__ mW2, const float* __restrict__ mb2,
       const float* __restrict__ mW3, const float* __restrict__ mb3,
       float* __restrict__ out)
{
    __shared__ float4 s_fs[2048];        // 32KB staged half-table (swizzled)
    __shared__ float  sred[8][32];
    __shared__ float  s_ap, s_an, s_beta;
    __shared__ int    s_fast;
    __shared__ float  sw1[H_DIM], sb1v[H_DIM], sw2[H_DIM * H_DIM], sb2v[H_DIM], sw3[H_DIM];

    const int tid = threadIdx.x;

    // ---- warp 0: fold m-MLP + zero-bias check (weights L2-hot) ----
    if (tid < 32) {
        const int g = tid & 15;
        float cp = 0.0f, cn = 0.0f;
        #pragma unroll
        for (int h = 0; h < H_DIM; h++) {
            const float w2 = __ldg(mW2 + g * H_DIM + h);
            const float w1 = __ldg(mW1 + h);
            cp = fmaf(w2, fmaxf(w1, 0.0f), cp);
            cn = fmaf(w2, fminf(w1, 0.0f), cn);
        }
        const float w3 = __ldg(mW3 + g);
        float ap = w3 * fmaxf(cp, 0.0f);
        float an = w3 * fminf(cn, 0.0f);
        #pragma unroll
        for (int off = 8; off > 0; off >>= 1) {
            ap += __shfl_xor_sync(0xFFFFFFFFu, ap, off);
            an += __shfl_xor_sync(0xFFFFFFFFu, an, off);
        }
        int z = (__ldg(mb1 + g) == 0.0f) & (__ldg(mb2 + g) == 0.0f);
        z = __all_sync(0xFFFFFFFFu, z);
        if (tid == 0) { s_ap = ap; s_an = an; s_beta = __ldg(mb3); s_fast = z; }
    }
    __syncthreads();

    const int i0 = blockIdx.x * 4;

    float acc[4][O_DIM];
    #pragma unroll
    for (int r = 0; r < 4; r++)
        #pragma unroll
        for (int o = 0; o < O_DIM; o++) acc[r][o] = 0.0f;

    if (s_fast) {
        const float ap = s_ap, an = s_an, be = s_beta;
        #pragma unroll
        for (int jt = 0; jt < 2; jt++) {
            // ---- stage 32KB of f_sums: coalesced GMEM -> swizzled SMEM ----
            const float4* src = (const float4*)(g_fsums + jt * 1024 * O_DIM);
            #pragma unroll
            for (int q = 0; q < 8; q++) {
                const int idx = q * 256 + tid;               // float4 index
                const unsigned off = (unsigned)idx * 16u;
                s_fs[(off ^ ((off >> 3) & 0x70u)) >> 4] = src[idx];
            }
            __syncthreads();

            // ---- own slice: 8 float4 via conflict-free LDS.128 ----
            float4 fs[8];
            #pragma unroll
            for (int q = 0; q < 8; q++) {
                const unsigned off = (unsigned)tid * 128u + q * 16u;
                fs[q] = s_fs[(off ^ ((off >> 3) & 0x70u)) >> 4];
            }
            __syncthreads();   // safe to overwrite s_fs next jt

            // ---- stream d/norm for 4 rows, accumulate ----
            const int j0 = jt * 1024 + tid * 4;
            float4 dv[4], nv[4];
            #pragma unroll
            for (int r = 0; r < 4; r++) {
                dv[r] = __ldcs((const float4*)(dmat + (size_t)(i0 + r) * N_NODES + j0));
                nv[r] = __ldcs((const float4*)(nmat + (size_t)(i0 + r) * N_NODES + j0));
            }

            #pragma unroll
            for (int r = 0; r < 4; r++) {
                const float w0 = __fdividef(fmaf(ap, fmaxf(dv[r].x, 0.f), fmaf(an, fminf(dv[r].x, 0.f), be)), nv[r].x);
                const float w1 = __fdividef(fmaf(ap, fmaxf(dv[r].y, 0.f), fmaf(an, fminf(dv[r].y, 0.f), be)), nv[r].y);
                const float w2 = __fdividef(fmaf(ap, fmaxf(dv[r].z, 0.f), fmaf(an, fminf(dv[r].z, 0.f), be)), nv[r].z);
                const float w3 = __fdividef(fmaf(ap, fmaxf(dv[r].w, 0.f), fmaf(an, fminf(dv[r].w, 0.f), be)), nv[r].w);
                #pragma unroll
                for (int o = 0; o < 4; o++) {
                    acc[r][o]   = fmaf(w0, (&fs[0].x)[o], acc[r][o]);
                    acc[r][4+o] = fmaf(w0, (&fs[1].x)[o], acc[r][4+o]);
                    acc[r][o]   = fmaf(w1, (&fs[2].x)[o], acc[r][o]);
                    acc[r][4+o] = fmaf(w1, (&fs[3].x)[o], acc[r][4+o]);
                    acc[r][o]   = fmaf(w2, (&fs[4].x)[o], acc[r][o]);
                    acc[r][4+o] = fmaf(w2, (&fs[5].x)[o], acc[r][4+o]);
                    acc[r][o]   = fmaf(w3, (&fs[6].x)[o], acc[r][o]);
                    acc[r][4+o] = fmaf(w3, (&fs[7].x)[o], acc[r][4+o]);
                }
            }
        }
    } else {
        // ---- honest fallback: full per-pair m-MLP (never taken here) ----
        if (tid < H_DIM) {
            sw1[tid]  = mW1[tid]; sb1v[tid] = mb1[tid];
            sb2v[tid] = mb2[tid]; sw3[tid]  = mW3[tid];
        }
        sw2[tid] = mW2[tid];
        __syncthreads();
        const float b3v = mb3[0];

        for (int jt = 0; jt < 2; jt++) {
            const int j0 = jt * 1024 + tid * 4;
            float4 fs[8];
            const float4* fp = (const float4*)(g_fsums + j0 * O_DIM);
            #pragma unroll
            for (int q = 0; q < 8; q++) fs[q] = fp[q];

            for (int r = 0; r < 4; r++) {
                const float4 d4 = *(const float4*)(dmat + (size_t)(i0 + r) * N_NODES + j0);
                const float4 n4 = *(const float4*)(nmat + (size_t)(i0 + r) * N_NODES + j0);
                float w[4];
                w[0] = __fdividef(m_eval_full(d4.x, sw1, sb1v, sw2, sb2v, sw3, b3v), n4.x);
                w[1] = __fdividef(m_eval_full(d4.y, sw1, sb1v, sw2, sb2v, sw3, b3v), n4.y);
                w[2] = __fdividef(m_eval_full(d4.z, sw1, sb1v, sw2, sb2v, sw3, b3v), n4.z);
                w[3] = __fdividef(m_eval_full(d4.w, sw1, sb1v, sw2, sb2v, sw3, b3v), n4.w);
                #pragma unroll
                for (int q = 0; q < 4; q++)
                    #pragma unroll
                    for (int o = 0; o < 4; o++) {
                        acc[r][o]   = fmaf(w[q], (&fs[q*2].x)[o],   acc[r][o]);
                        acc[r][4+o] = fmaf(w[q], (&fs[q*2+1].x)[o], acc[r][4+o]);
                    }
            }
        }
    }

    // ---- block reduction: warp butterfly, then 8 warps via smem ----
    #pragma unroll
    for (int r = 0; r < 4; r++)
        #pragma unroll
        for (int o = 0; o < O_DIM; o++)
            #pragma unroll
            for (int off = 16; off > 0; off >>= 1)
                acc[r][o] += __shfl_xor_sync(0xFFFFFFFFu, acc[r][o], off);

    const int warp = tid >> 5;
    const int lane = tid & 31;
    if (lane == 0) {
        #pragma unroll
        for (int r = 0; r < 4; r++)
            #pragma unroll
            for (int o = 0; o < O_DIM; o++)
                sred[warp][r * O_DIM + o] = acc[r][o];
    }
    __syncthreads();
    if (tid < 32) {
        float s = 0.0f;
        #pragma unroll
        for (int w = 0; w < 8; w++) s += sred[w][tid];
        const int r = tid >> 3;
        const int o = tid & 7;
        out[(i0 + r) * O_DIM + o] = s;
    }
}

// ============================================================================
// launch
// ============================================================================
extern "C" void kernel_launch(void* const* d_in, const int* in_sizes, int n_in,
                              void* d_out, int out_size)
{
    const float* x   = (const float*)d_in[0];
    const float* dm  = (const float*)d_in[1];
    const float* nm  = (const float*)d_in[2];
    const float* fW1 = (const float*)d_in[3];
    const float* fb1 = (const float*)d_in[4];
    const float* fW2 = (const float*)d_in[5];
    const float* fb2 = (const float*)d_in[6];
    const float* fW3 = (const float*)d_in[7];
    const float* fb3 = (const float*)d_in[8];
    const float* mW1 = (const float*)d_in[9];
    const float* mb1 = (const float*)d_in[10];
    const float* mW2 = (const float*)d_in[11];
    const float* mb2 = (const float*)d_in[12];
    const float* mW3 = (const float*)d_in[13];
    const float* mb3 = (const float*)d_in[14];
    float* out = (float*)d_out;

    k_fsum<<<128, 256>>>(x, fW1, fb1, fW2, fb2, fW3, fb3);
    k_main<<<512, 256>>>(dm, nm, mW1, mb1, mW2, mb2, mW3, mb3, out);
}